// round 2
// baseline (speedup 1.0000x reference)
#include <cuda_runtime.h>
#include <cstdint>

// Problem constants
#define NTOK   4096          // B*L
#define DIM    2048
#define NH     16
#define HDIM   128
#define LSEQ   2048
#define NB     2
#define QKVDIM 6144

// -------- scratch (device globals; no allocation allowed) --------
__device__ float g_xn[(size_t)NTOK * DIM];       // rmsnorm out (reused for yn)
__device__ float g_qkv[(size_t)NTOK * QKVDIM];   // qkv projections
__device__ float g_attn[(size_t)NTOK * DIM];     // attention output (merged heads)
__device__ float g_after[(size_t)NTOK * DIM];    // x + attn_out
__device__ float g_hidden[(size_t)NTOK * DIM];   // relu(yn @ w_in^T)
__device__ float g_hg[(size_t)NTOK * DIM];       // hidden * gate

// ============================================================================
// RMSNorm: one block per row of 2048
// ============================================================================
__global__ __launch_bounds__(256) void rmsnorm_k(const float* __restrict__ x,
                                                 const float* __restrict__ g,
                                                 float* __restrict__ y) {
    __shared__ float red[8];
    const size_t base = (size_t)blockIdx.x * DIM;
    const int tid = threadIdx.x;
    float4 v0 = *(const float4*)(x + base + tid * 4);
    float4 v1 = *(const float4*)(x + base + 1024 + tid * 4);
    float s = v0.x*v0.x + v0.y*v0.y + v0.z*v0.z + v0.w*v0.w
            + v1.x*v1.x + v1.y*v1.y + v1.z*v1.z + v1.w*v1.w;
    #pragma unroll
    for (int o = 16; o; o >>= 1) s += __shfl_xor_sync(0xFFFFFFFFu, s, o);
    if ((tid & 31) == 0) red[tid >> 5] = s;
    __syncthreads();
    float tot = 0.f;
    #pragma unroll
    for (int i = 0; i < 8; i++) tot += red[i];
    const float norm = rsqrtf(tot * (1.0f / DIM) + 1e-6f);
    float4 g0 = *(const float4*)(g + tid * 4);
    float4 g1 = *(const float4*)(g + 1024 + tid * 4);
    float4 o0, o1;
    o0.x = v0.x * norm * g0.x; o0.y = v0.y * norm * g0.y;
    o0.z = v0.z * norm * g0.z; o0.w = v0.w * norm * g0.w;
    o1.x = v1.x * norm * g1.x; o1.y = v1.y * norm * g1.y;
    o1.z = v1.z * norm * g1.z; o1.w = v1.w * norm * g1.w;
    *(float4*)(y + base + tid * 4) = o0;
    *(float4*)(y + base + 1024 + tid * 4) = o1;
}

// ============================================================================
// Row softmax over 2048 contiguous elements, in place
// ============================================================================
__global__ __launch_bounds__(256) void softmax_k(float* __restrict__ S) {
    __shared__ float red[8];
    const size_t base = (size_t)blockIdx.x * LSEQ;
    const int tid = threadIdx.x;
    float4 v0 = *(float4*)(S + base + tid * 4);
    float4 v1 = *(float4*)(S + base + 1024 + tid * 4);
    float m = fmaxf(fmaxf(fmaxf(v0.x, v0.y), fmaxf(v0.z, v0.w)),
                    fmaxf(fmaxf(v1.x, v1.y), fmaxf(v1.z, v1.w)));
    #pragma unroll
    for (int o = 16; o; o >>= 1) m = fmaxf(m, __shfl_xor_sync(0xFFFFFFFFu, m, o));
    if ((tid & 31) == 0) red[tid >> 5] = m;
    __syncthreads();
    float mx = red[0];
    #pragma unroll
    for (int i = 1; i < 8; i++) mx = fmaxf(mx, red[i]);
    __syncthreads();
    v0.x = __expf(v0.x - mx); v0.y = __expf(v0.y - mx);
    v0.z = __expf(v0.z - mx); v0.w = __expf(v0.w - mx);
    v1.x = __expf(v1.x - mx); v1.y = __expf(v1.y - mx);
    v1.z = __expf(v1.z - mx); v1.w = __expf(v1.w - mx);
    float s = v0.x + v0.y + v0.z + v0.w + v1.x + v1.y + v1.z + v1.w;
    #pragma unroll
    for (int o = 16; o; o >>= 1) s += __shfl_xor_sync(0xFFFFFFFFu, s, o);
    if ((tid & 31) == 0) red[tid >> 5] = s;
    __syncthreads();
    float tot = 0.f;
    #pragma unroll
    for (int i = 0; i < 8; i++) tot += red[i];
    const float inv = 1.0f / tot;
    v0.x *= inv; v0.y *= inv; v0.z *= inv; v0.w *= inv;
    v1.x *= inv; v1.y *= inv; v1.z *= inv; v1.w *= inv;
    *(float4*)(S + base + tid * 4) = v0;
    *(float4*)(S + base + 1024 + tid * 4) = v1;
}

// ============================================================================
// Tiled SGEMM: C = epilogue(alpha * A @ op(B)) , 128x128 tile, BK=8, 8x8/thread
//   TRANSB=true : C[m,n] = sum_k A[m,k] * B[n,k]
//   TRANSB=false: C[m,n] = sum_k A[m,k] * B[k,n]
// Batched over blockIdx.z with two-level offsets: off = (z/zdiv)*so + (z%zdiv)*si
// EPI: 0=none, 1=add Dm, 2=relu, 3=mul by Dm
// All of M, N divisible by 128; K divisible by 8. No bounds checks.
// ============================================================================
template <int EPI, bool TRANSB>
__global__ __launch_bounds__(256) void sgemm_k(
    const float* __restrict__ A, int lda, size_t soA, size_t siA,
    const float* __restrict__ B, int ldb, size_t soB, size_t siB,
    float* __restrict__ C, int ldc, size_t soC, size_t siC,
    const float* __restrict__ Dm, int ldd, size_t soD, size_t siD,
    int K, int zdiv, float alpha) {

    __shared__ float As[8][128];
    __shared__ float Bs[8][128];

    const int z = blockIdx.z;
    const int zo = z / zdiv, zi = z % zdiv;
    A += (size_t)zo * soA + (size_t)zi * siA;
    B += (size_t)zo * soB + (size_t)zi * siB;
    C += (size_t)zo * soC + (size_t)zi * siC;
    if (EPI == 1 || EPI == 3) Dm += (size_t)zo * soD + (size_t)zi * siD;

    const int m0 = blockIdx.y * 128;
    const int n0 = blockIdx.x * 128;
    const int tid = threadIdx.x;
    const int tm = (tid >> 4) * 8;   // 0..120
    const int tn = (tid & 15) * 8;   // 0..120

    const int ar = tid >> 1;         // 0..127
    const int ac = (tid & 1) * 4;    // 0 or 4
    const int bk = tid >> 5;         // 0..7
    const int bn = (tid & 31) * 4;   // 0..124

    float acc[8][8];
    #pragma unroll
    for (int i = 0; i < 8; i++)
        #pragma unroll
        for (int j = 0; j < 8; j++) acc[i][j] = 0.f;

    for (int k0 = 0; k0 < K; k0 += 8) {
        float4 a4 = *(const float4*)(A + (size_t)(m0 + ar) * lda + k0 + ac);
        As[ac + 0][ar] = a4.x; As[ac + 1][ar] = a4.y;
        As[ac + 2][ar] = a4.z; As[ac + 3][ar] = a4.w;
        if (TRANSB) {
            float4 b4 = *(const float4*)(B + (size_t)(n0 + ar) * ldb + k0 + ac);
            Bs[ac + 0][ar] = b4.x; Bs[ac + 1][ar] = b4.y;
            Bs[ac + 2][ar] = b4.z; Bs[ac + 3][ar] = b4.w;
        } else {
            float4 b4 = *(const float4*)(B + (size_t)(k0 + bk) * ldb + n0 + bn);
            *(float4*)&Bs[bk][bn] = b4;
        }
        __syncthreads();
        #pragma unroll
        for (int kk = 0; kk < 8; kk++) {
            float a[8], b[8];
            #pragma unroll
            for (int i = 0; i < 8; i++) a[i] = As[kk][tm + i];
            #pragma unroll
            for (int j = 0; j < 8; j++) b[j] = Bs[kk][tn + j];
            #pragma unroll
            for (int i = 0; i < 8; i++)
                #pragma unroll
                for (int j = 0; j < 8; j++)
                    acc[i][j] = fmaf(a[i], b[j], acc[i][j]);
        }
        __syncthreads();
    }

    #pragma unroll
    for (int i = 0; i < 8; i++) {
        const size_t row = (size_t)(m0 + tm + i);
        #pragma unroll
        for (int j = 0; j < 8; j += 4) {
            float4 v;
            v.x = acc[i][j + 0] * alpha;
            v.y = acc[i][j + 1] * alpha;
            v.z = acc[i][j + 2] * alpha;
            v.w = acc[i][j + 3] * alpha;
            if (EPI == 1) {
                float4 d4 = *(const float4*)(Dm + row * ldd + n0 + tn + j);
                v.x += d4.x; v.y += d4.y; v.z += d4.z; v.w += d4.w;
            } else if (EPI == 2) {
                v.x = fmaxf(v.x, 0.f); v.y = fmaxf(v.y, 0.f);
                v.z = fmaxf(v.z, 0.f); v.w = fmaxf(v.w, 0.f);
            } else if (EPI == 3) {
                float4 d4 = *(const float4*)(Dm + row * ldd + n0 + tn + j);
                v.x *= d4.x; v.y *= d4.y; v.z *= d4.z; v.w *= d4.w;
            }
            *(float4*)(C + row * ldc + n0 + tn + j) = v;
        }
    }
}

// ============================================================================
// Host launcher
// ============================================================================
extern "C" void kernel_launch(void* const* d_in, const int* in_sizes, int n_in,
                              void* d_out, int out_size) {
    const float* x          = (const float*)d_in[0];
    const float* w_qkv      = (const float*)d_in[1];
    const float* w_out      = (const float*)d_in[2];
    const float* w_in       = (const float*)d_in[3];
    const float* w_hidden   = (const float*)d_in[4];
    const float* w_gate     = (const float*)d_in[5];
    const float* g_attnnorm = (const float*)d_in[6];
    const float* g_ffnnorm  = (const float*)d_in[7];

    float* out    = (float*)d_out;                       // [B, L, D]
    float* scores = out + (size_t)NTOK * DIM;            // [B, H, L, L]

    float *xn, *qkv, *attn, *after, *hidden, *hg;
    cudaGetSymbolAddress((void**)&xn,     g_xn);
    cudaGetSymbolAddress((void**)&qkv,    g_qkv);
    cudaGetSymbolAddress((void**)&attn,   g_attn);
    cudaGetSymbolAddress((void**)&after,  g_after);
    cudaGetSymbolAddress((void**)&hidden, g_hidden);
    cudaGetSymbolAddress((void**)&hg,     g_hg);

    const size_t slabS  = (size_t)LSEQ * LSEQ;       // per-(b,h) score slab
    const size_t bQKV   = (size_t)LSEQ * QKVDIM;     // per-batch qkv slab
    const size_t bTOK   = (size_t)LSEQ * DIM;        // per-batch token slab
    const float invsqrt = 0.08838834764831845f;      // 1/sqrt(128)

    // 1) attn rmsnorm
    rmsnorm_k<<<NTOK, 256>>>(x, g_attnnorm, xn);

    // 2) qkv = xn @ w_qkv^T   [4096, 6144]
    sgemm_k<0, true><<<dim3(QKVDIM / 128, NTOK / 128, 1), 256>>>(
        xn, DIM, 0, 0, w_qkv, DIM, 0, 0, qkv, QKVDIM, 0, 0,
        nullptr, 0, 0, 0, DIM, 1, 1.0f);

    // 3) scores = (Q @ K^T) / sqrt(HD), z = b*16+h
    sgemm_k<0, true><<<dim3(LSEQ / 128, LSEQ / 128, NB * NH), 256>>>(
        qkv,            QKVDIM, bQKV, HDIM,         // Q: qkv[:, h*128 + ...]
        qkv + DIM,      QKVDIM, bQKV, HDIM,         // K
        scores,         LSEQ,   (size_t)NH * slabS, slabS,
        nullptr, 0, 0, 0, HDIM, NH, invsqrt);

    // 4) softmax over last axis (65536 rows of 2048)
    softmax_k<<<NB * NH * LSEQ, 256>>>(scores);

    // 5) attn = scores @ V  -> merged-head layout [4096, 2048]
    sgemm_k<0, false><<<dim3(1, LSEQ / 128, NB * NH), 256>>>(
        scores,         LSEQ,   (size_t)NH * slabS, slabS,
        qkv + 2 * DIM,  QKVDIM, bQKV, HDIM,         // V rows (tokens) x 128
        attn,           DIM,    bTOK, HDIM,
        nullptr, 0, 0, 0, LSEQ, NH, 1.0f);

    // 6) after_attn = x + attn @ w_out^T
    sgemm_k<1, true><<<dim3(DIM / 128, NTOK / 128, 1), 256>>>(
        attn, DIM, 0, 0, w_out, DIM, 0, 0, after, DIM, 0, 0,
        x, DIM, 0, 0, DIM, 1, 1.0f);

    // 7) ffn rmsnorm (reuse xn as yn)
    rmsnorm_k<<<NTOK, 256>>>(after, g_ffnnorm, xn);

    // 8) hidden = relu(yn @ w_in^T)
    sgemm_k<2, true><<<dim3(DIM / 128, NTOK / 128, 1), 256>>>(
        xn, DIM, 0, 0, w_in, DIM, 0, 0, hidden, DIM, 0, 0,
        nullptr, 0, 0, 0, DIM, 1, 1.0f);

    // 9) hg = hidden * (hidden @ w_gate^T)
    sgemm_k<3, true><<<dim3(DIM / 128, NTOK / 128, 1), 256>>>(
        hidden, DIM, 0, 0, w_gate, DIM, 0, 0, hg, DIM, 0, 0,
        hidden, DIM, 0, 0, DIM, 1, 1.0f);

    // 10) out = after_attn + hg @ w_hidden^T   (written straight into d_out)
    sgemm_k<1, true><<<dim3(DIM / 128, NTOK / 128, 1), 256>>>(
        hg, DIM, 0, 0, w_hidden, DIM, 0, 0, out, DIM, 0, 0,
        after, DIM, 0, 0, DIM, 1, 1.0f);
}

// round 4
// speedup vs baseline: 2.2877x; 2.2877x over previous
#include <cuda_runtime.h>
#include <cstdint>

// Problem constants
#define NTOK   4096          // B*L
#define DIM    2048
#define NH     16
#define HDIM   128
#define LSEQ   2048
#define NB     2
#define QKVDIM 6144

// -------- scratch (device globals; no allocation allowed) --------
__device__ float g_xn[(size_t)NTOK * DIM];
__device__ float g_qkv[(size_t)NTOK * QKVDIM];
__device__ float g_attn[(size_t)NTOK * DIM];
__device__ float g_after[(size_t)NTOK * DIM];
__device__ float g_hidden[(size_t)NTOK * DIM];
__device__ float g_hg[(size_t)NTOK * DIM];
__device__ float g_vt[(size_t)NB * NH * HDIM * LSEQ];   // V^T per head (K-major)

// ============================================================================
// RMSNorm: one block per row of 2048
// ============================================================================
__global__ __launch_bounds__(256) void rmsnorm_k(const float* __restrict__ x,
                                                 const float* __restrict__ g,
                                                 float* __restrict__ y) {
    __shared__ float red[8];
    const size_t base = (size_t)blockIdx.x * DIM;
    const int tid = threadIdx.x;
    float4 v0 = *(const float4*)(x + base + tid * 4);
    float4 v1 = *(const float4*)(x + base + 1024 + tid * 4);
    float s = v0.x*v0.x + v0.y*v0.y + v0.z*v0.z + v0.w*v0.w
            + v1.x*v1.x + v1.y*v1.y + v1.z*v1.z + v1.w*v1.w;
    #pragma unroll
    for (int o = 16; o; o >>= 1) s += __shfl_xor_sync(0xFFFFFFFFu, s, o);
    if ((tid & 31) == 0) red[tid >> 5] = s;
    __syncthreads();
    float tot = 0.f;
    #pragma unroll
    for (int i = 0; i < 8; i++) tot += red[i];
    const float norm = rsqrtf(tot * (1.0f / DIM) + 1e-6f);
    float4 g0 = *(const float4*)(g + tid * 4);
    float4 g1 = *(const float4*)(g + 1024 + tid * 4);
    float4 o0, o1;
    o0.x = v0.x * norm * g0.x; o0.y = v0.y * norm * g0.y;
    o0.z = v0.z * norm * g0.z; o0.w = v0.w * norm * g0.w;
    o1.x = v1.x * norm * g1.x; o1.y = v1.y * norm * g1.y;
    o1.z = v1.z * norm * g1.z; o1.w = v1.w * norm * g1.w;
    *(float4*)(y + base + tid * 4) = o0;
    *(float4*)(y + base + 1024 + tid * 4) = o1;
}

// ============================================================================
// Row softmax over 2048, in place (86% DRAM — keep)
// ============================================================================
__global__ __launch_bounds__(256) void softmax_k(float* __restrict__ S) {
    __shared__ float red[8];
    const size_t base = (size_t)blockIdx.x * LSEQ;
    const int tid = threadIdx.x;
    float4 v0 = *(float4*)(S + base + tid * 4);
    float4 v1 = *(float4*)(S + base + 1024 + tid * 4);
    float m = fmaxf(fmaxf(fmaxf(v0.x, v0.y), fmaxf(v0.z, v0.w)),
                    fmaxf(fmaxf(v1.x, v1.y), fmaxf(v1.z, v1.w)));
    #pragma unroll
    for (int o = 16; o; o >>= 1) m = fmaxf(m, __shfl_xor_sync(0xFFFFFFFFu, m, o));
    if ((tid & 31) == 0) red[tid >> 5] = m;
    __syncthreads();
    float mx = red[0];
    #pragma unroll
    for (int i = 1; i < 8; i++) mx = fmaxf(mx, red[i]);
    __syncthreads();
    v0.x = __expf(v0.x - mx); v0.y = __expf(v0.y - mx);
    v0.z = __expf(v0.z - mx); v0.w = __expf(v0.w - mx);
    v1.x = __expf(v1.x - mx); v1.y = __expf(v1.y - mx);
    v1.z = __expf(v1.z - mx); v1.w = __expf(v1.w - mx);
    float s = v0.x + v0.y + v0.z + v0.w + v1.x + v1.y + v1.z + v1.w;
    #pragma unroll
    for (int o = 16; o; o >>= 1) s += __shfl_xor_sync(0xFFFFFFFFu, s, o);
    if ((tid & 31) == 0) red[tid >> 5] = s;
    __syncthreads();
    float tot = 0.f;
    #pragma unroll
    for (int i = 0; i < 8; i++) tot += red[i];
    const float inv = 1.0f / tot;
    v0.x *= inv; v0.y *= inv; v0.z *= inv; v0.w *= inv;
    v1.x *= inv; v1.y *= inv; v1.z *= inv; v1.w *= inv;
    *(float4*)(S + base + tid * 4) = v0;
    *(float4*)(S + base + 1024 + tid * 4) = v1;
}

// ============================================================================
// Transpose V per (b,h): vt[z][d][t] = qkv[b*L+t][2D + h*128 + d]
// ============================================================================
__global__ __launch_bounds__(256) void transpose_v_k(const float* __restrict__ qkv,
                                                     float* __restrict__ vt) {
    __shared__ float tile[32][33];
    const int z = blockIdx.z, zo = z >> 4, zi = z & 15;
    const float* src = qkv + (size_t)zo * LSEQ * QKVDIM + 2 * DIM + zi * HDIM;
    float* dst = vt + (size_t)z * HDIM * LSEQ;
    const int t0 = blockIdx.x * 32, d0 = blockIdx.y * 32;
    const int tx = threadIdx.x & 31, ty = threadIdx.x >> 5;
    #pragma unroll
    for (int r = ty; r < 32; r += 8)
        tile[r][tx] = src[(size_t)(t0 + r) * QKVDIM + d0 + tx];
    __syncthreads();
    #pragma unroll
    for (int r = ty; r < 32; r += 8)
        dst[(size_t)(d0 + r) * LSEQ + t0 + tx] = tile[tx][r];
}

// ============================================================================
// tf32 tensor-core GEMM via mma.sync (sm_80 path, valid on base sm_103):
//   C = epi(alpha * A @ B^T); A:[M,K] row-major, B:[N,K] row-major.
//   BM=BN=128, BK=32. 8 warps (2x4), warp tile 64x32, m16n8k8 frags.
//   SMEM stride 36 floats (conflict-free frag loads). Double buffered.
//   Batched over z with two-level offsets. EPI: 0=none 1=+Dm 2=relu 3=*Dm
// ============================================================================
#define TSTRIDE 36
#define TILE_W  (128 * TSTRIDE)            // words per tile = 4608
#define SM_TOT  (4 * TILE_W * 4)           // bytes = 73728

__device__ __forceinline__ uint32_t f2tf(float f) {
    uint32_t u;
    asm("cvt.rna.tf32.f32 %0, %1;" : "=r"(u) : "f"(f));
    return u;
}

__device__ __forceinline__ void mma8(float c[4], const uint32_t a[4],
                                     uint32_t b0, uint32_t b1) {
    asm volatile(
        "mma.sync.aligned.m16n8k8.row.col.f32.tf32.tf32.f32 "
        "{%0,%1,%2,%3}, {%4,%5,%6,%7}, {%8,%9}, {%0,%1,%2,%3};"
        : "+f"(c[0]), "+f"(c[1]), "+f"(c[2]), "+f"(c[3])
        : "r"(a[0]), "r"(a[1]), "r"(a[2]), "r"(a[3]), "r"(b0), "r"(b1));
}

__device__ __forceinline__ void ld_tile(const float* __restrict__ P, int ld,
                                        int row0, int k0, int tid, float4 v[4]) {
    #pragma unroll
    for (int r = 0; r < 4; r++) {
        int idx = tid + 256 * r;
        int row = idx >> 3, c4 = idx & 7;
        v[r] = *(const float4*)(P + (size_t)(row0 + row) * ld + k0 + c4 * 4);
    }
}

__device__ __forceinline__ void st_tile(uint32_t* __restrict__ S, int tid,
                                        const float4 v[4]) {
    #pragma unroll
    for (int r = 0; r < 4; r++) {
        int idx = tid + 256 * r;
        int row = idx >> 3, c4 = idx & 7;
        uint4 u;
        u.x = f2tf(v[r].x); u.y = f2tf(v[r].y);
        u.z = f2tf(v[r].z); u.w = f2tf(v[r].w);
        *(uint4*)(S + row * TSTRIDE + c4 * 4) = u;
    }
}

template <int EPI>
__global__ __launch_bounds__(256) void tfgemm_k(
    const float* __restrict__ A, int lda, size_t soA, size_t siA,
    const float* __restrict__ B, int ldb, size_t soB, size_t siB,
    float* __restrict__ C, int ldc, size_t soC, size_t siC,
    const float* __restrict__ Dm, int ldd, size_t soD, size_t siD,
    int K, int zdiv, float alpha) {

    extern __shared__ uint32_t smw[];
    uint32_t* SA[2] = { smw,             smw + TILE_W };
    uint32_t* SB[2] = { smw + 2*TILE_W,  smw + 3*TILE_W };

    const int tid = threadIdx.x, wid = tid >> 5, lane = tid & 31;
    const int qr = lane >> 2, qc = lane & 3;
    const int wm = (wid >> 2) * 64;   // 0 or 64
    const int wn = (wid & 3) * 32;    // 0,32,64,96

    const int z = blockIdx.z, zo = z / zdiv, zi = z % zdiv;
    A += (size_t)zo * soA + (size_t)zi * siA;
    B += (size_t)zo * soB + (size_t)zi * siB;
    C += (size_t)zo * soC + (size_t)zi * siC;
    if (EPI == 1 || EPI == 3) Dm += (size_t)zo * soD + (size_t)zi * siD;

    const int m0 = blockIdx.y * 128;
    const int n0 = blockIdx.x * 128;

    float acc[4][4][4];
    #pragma unroll
    for (int i = 0; i < 4; i++)
        #pragma unroll
        for (int j = 0; j < 4; j++)
            #pragma unroll
            for (int r = 0; r < 4; r++) acc[i][j][r] = 0.f;

    float4 pa[4], pb[4];
    ld_tile(A, lda, m0, 0, tid, pa);
    ld_tile(B, ldb, n0, 0, tid, pb);
    st_tile(SA[0], tid, pa);
    st_tile(SB[0], tid, pb);
    __syncthreads();

    const int T = K / 32;
    int b = 0;
    for (int i = 0; i < T; i++) {
        if (i + 1 < T) {
            ld_tile(A, lda, m0, (i + 1) * 32, tid, pa);
            ld_tile(B, ldb, n0, (i + 1) * 32, tid, pb);
        }
        const uint32_t* As = SA[b];
        const uint32_t* Bs = SB[b];
        #pragma unroll
        for (int ks = 0; ks < 4; ks++) {
            const int kb = ks * 8;
            uint32_t af[4][4];
            #pragma unroll
            for (int mf = 0; mf < 4; mf++) {
                const uint32_t* p = As + (wm + mf * 16 + qr) * TSTRIDE + kb + qc;
                af[mf][0] = p[0];
                af[mf][1] = p[8 * TSTRIDE];
                af[mf][2] = p[4];
                af[mf][3] = p[8 * TSTRIDE + 4];
            }
            #pragma unroll
            for (int nf = 0; nf < 4; nf++) {
                const uint32_t* p = Bs + (wn + nf * 8 + qr) * TSTRIDE + kb + qc;
                uint32_t b0 = p[0], b1 = p[4];
                #pragma unroll
                for (int mf = 0; mf < 4; mf++)
                    mma8(acc[mf][nf], af[mf], b0, b1);
            }
        }
        if (i + 1 < T) {
            st_tile(SA[b ^ 1], tid, pa);
            st_tile(SB[b ^ 1], tid, pb);
        }
        __syncthreads();
        b ^= 1;
    }

    // epilogue: c0/c1 -> (row, col/col+1); c2/c3 -> (row+8, col/col+1)
    #pragma unroll
    for (int mf = 0; mf < 4; mf++) {
        #pragma unroll
        for (int half = 0; half < 2; half++) {
            const size_t row = (size_t)(m0 + wm + mf * 16 + qr + half * 8);
            #pragma unroll
            for (int nf = 0; nf < 4; nf++) {
                const int col = n0 + wn + nf * 8 + qc * 2;
                float2 v;
                v.x = acc[mf][nf][half * 2 + 0] * alpha;
                v.y = acc[mf][nf][half * 2 + 1] * alpha;
                if (EPI == 1) {
                    float2 d2 = *(const float2*)(Dm + row * ldd + col);
                    v.x += d2.x; v.y += d2.y;
                } else if (EPI == 2) {
                    v.x = fmaxf(v.x, 0.f); v.y = fmaxf(v.y, 0.f);
                } else if (EPI == 3) {
                    float2 d2 = *(const float2*)(Dm + row * ldd + col);
                    v.x *= d2.x; v.y *= d2.y;
                }
                *(float2*)(C + row * ldc + col) = v;
            }
        }
    }
}

// ============================================================================
// Host launcher
// ============================================================================
extern "C" void kernel_launch(void* const* d_in, const int* in_sizes, int n_in,
                              void* d_out, int out_size) {
    const float* x          = (const float*)d_in[0];
    const float* w_qkv      = (const float*)d_in[1];
    const float* w_out      = (const float*)d_in[2];
    const float* w_in       = (const float*)d_in[3];
    const float* w_hidden   = (const float*)d_in[4];
    const float* w_gate     = (const float*)d_in[5];
    const float* g_attnnorm = (const float*)d_in[6];
    const float* g_ffnnorm  = (const float*)d_in[7];

    float* out    = (float*)d_out;
    float* scores = out + (size_t)NTOK * DIM;

    float *xn, *qkv, *attn, *after, *hidden, *hg, *vt;
    cudaGetSymbolAddress((void**)&xn,     g_xn);
    cudaGetSymbolAddress((void**)&qkv,    g_qkv);
    cudaGetSymbolAddress((void**)&attn,   g_attn);
    cudaGetSymbolAddress((void**)&after,  g_after);
    cudaGetSymbolAddress((void**)&hidden, g_hidden);
    cudaGetSymbolAddress((void**)&hg,     g_hg);
    cudaGetSymbolAddress((void**)&vt,     g_vt);

    static bool attr_done = false;
    if (!attr_done) {
        cudaFuncSetAttribute(tfgemm_k<0>, cudaFuncAttributeMaxDynamicSharedMemorySize, SM_TOT);
        cudaFuncSetAttribute(tfgemm_k<1>, cudaFuncAttributeMaxDynamicSharedMemorySize, SM_TOT);
        cudaFuncSetAttribute(tfgemm_k<2>, cudaFuncAttributeMaxDynamicSharedMemorySize, SM_TOT);
        cudaFuncSetAttribute(tfgemm_k<3>, cudaFuncAttributeMaxDynamicSharedMemorySize, SM_TOT);
        attr_done = true;
    }

    const size_t slabS = (size_t)LSEQ * LSEQ;
    const size_t bQKV  = (size_t)LSEQ * QKVDIM;
    const size_t bTOK  = (size_t)LSEQ * DIM;
    const size_t hVT   = (size_t)HDIM * LSEQ;
    const float invsqrt = 0.08838834764831845f;   // 1/sqrt(128)

    // 1) attn rmsnorm
    rmsnorm_k<<<NTOK, 256>>>(x, g_attnnorm, xn);

    // 2) qkv = xn @ w_qkv^T : M=4096, N=6144, K=2048
    tfgemm_k<0><<<dim3(QKVDIM / 128, NTOK / 128, 1), 256, SM_TOT>>>(
        xn, DIM, 0, 0, w_qkv, DIM, 0, 0, qkv, QKVDIM, 0, 0,
        nullptr, 0, 0, 0, DIM, 1, 1.0f);

    // 3) transpose V per head (K-major B for attn@V)
    transpose_v_k<<<dim3(LSEQ / 32, HDIM / 32, NB * NH), 256>>>(qkv, vt);

    // 4) scores = (Q @ K^T)/sqrt(HD) : per z, M=N=2048, K=128
    tfgemm_k<0><<<dim3(LSEQ / 128, LSEQ / 128, NB * NH), 256, SM_TOT>>>(
        qkv,       QKVDIM, bQKV, HDIM,
        qkv + DIM, QKVDIM, bQKV, HDIM,
        scores,    LSEQ,   (size_t)NH * slabS, slabS,
        nullptr, 0, 0, 0, HDIM, NH, invsqrt);

    // 5) softmax
    softmax_k<<<NB * NH * LSEQ, 256>>>(scores);

    // 6) attn = scores @ V : per z, M=2048, N=128, K=2048
    tfgemm_k<0><<<dim3(1, LSEQ / 128, NB * NH), 256, SM_TOT>>>(
        scores, LSEQ, (size_t)NH * slabS, slabS,
        vt,     LSEQ, (size_t)NH * hVT,   hVT,
        attn,   DIM,  bTOK, HDIM,
        nullptr, 0, 0, 0, LSEQ, NH, 1.0f);

    // 7) after = x + attn @ w_out^T
    tfgemm_k<1><<<dim3(DIM / 128, NTOK / 128, 1), 256, SM_TOT>>>(
        attn, DIM, 0, 0, w_out, DIM, 0, 0, after, DIM, 0, 0,
        x, DIM, 0, 0, DIM, 1, 1.0f);

    // 8) ffn rmsnorm
    rmsnorm_k<<<NTOK, 256>>>(after, g_ffnnorm, xn);

    // 9) hidden = relu(yn @ w_in^T)
    tfgemm_k<2><<<dim3(DIM / 128, NTOK / 128, 1), 256, SM_TOT>>>(
        xn, DIM, 0, 0, w_in, DIM, 0, 0, hidden, DIM, 0, 0,
        nullptr, 0, 0, 0, DIM, 1, 1.0f);

    // 10) hg = hidden * (hidden @ w_gate^T)
    tfgemm_k<3><<<dim3(DIM / 128, NTOK / 128, 1), 256, SM_TOT>>>(
        hidden, DIM, 0, 0, w_gate, DIM, 0, 0, hg, DIM, 0, 0,
        hidden, DIM, 0, 0, DIM, 1, 1.0f);

    // 11) out = after + hg @ w_hidden^T
    tfgemm_k<1><<<dim3(DIM / 128, NTOK / 128, 1), 256, SM_TOT>>>(
        hg, DIM, 0, 0, w_hidden, DIM, 0, 0, out, DIM, 0, 0,
        after, DIM, 0, 0, DIM, 1, 1.0f);
}

// round 5
// speedup vs baseline: 3.5028x; 1.5311x over previous
#include <cuda_runtime.h>
#include <cstdint>

// Problem constants
#define NTOK   4096          // B*L
#define DIM    2048
#define NH     16
#define HDIM   128
#define LSEQ   2048
#define NB     2
#define QKVDIM 6144

// -------- scratch (device globals; no allocation allowed) --------
__device__ float g_xn[(size_t)NTOK * DIM];
__device__ float g_qkv[(size_t)NTOK * QKVDIM];
__device__ float g_attn[(size_t)NTOK * DIM];
__device__ float g_after[(size_t)NTOK * DIM];
__device__ float g_hidden[(size_t)NTOK * DIM];
__device__ float g_hg[(size_t)NTOK * DIM];
__device__ float g_vt[(size_t)NB * NH * HDIM * LSEQ];   // V^T per head (K-major)

// ============================================================================
// RMSNorm: one block per row of 2048
// ============================================================================
__global__ __launch_bounds__(256) void rmsnorm_k(const float* __restrict__ x,
                                                 const float* __restrict__ g,
                                                 float* __restrict__ y) {
    __shared__ float red[8];
    const size_t base = (size_t)blockIdx.x * DIM;
    const int tid = threadIdx.x;
    float4 v0 = *(const float4*)(x + base + tid * 4);
    float4 v1 = *(const float4*)(x + base + 1024 + tid * 4);
    float s = v0.x*v0.x + v0.y*v0.y + v0.z*v0.z + v0.w*v0.w
            + v1.x*v1.x + v1.y*v1.y + v1.z*v1.z + v1.w*v1.w;
    #pragma unroll
    for (int o = 16; o; o >>= 1) s += __shfl_xor_sync(0xFFFFFFFFu, s, o);
    if ((tid & 31) == 0) red[tid >> 5] = s;
    __syncthreads();
    float tot = 0.f;
    #pragma unroll
    for (int i = 0; i < 8; i++) tot += red[i];
    const float norm = rsqrtf(tot * (1.0f / DIM) + 1e-6f);
    float4 g0 = *(const float4*)(g + tid * 4);
    float4 g1 = *(const float4*)(g + 1024 + tid * 4);
    float4 o0, o1;
    o0.x = v0.x * norm * g0.x; o0.y = v0.y * norm * g0.y;
    o0.z = v0.z * norm * g0.z; o0.w = v0.w * norm * g0.w;
    o1.x = v1.x * norm * g1.x; o1.y = v1.y * norm * g1.y;
    o1.z = v1.z * norm * g1.z; o1.w = v1.w * norm * g1.w;
    *(float4*)(y + base + tid * 4) = o0;
    *(float4*)(y + base + 1024 + tid * 4) = o1;
}

// ============================================================================
// Row softmax over 2048, in place (86% DRAM — keep)
// ============================================================================
__global__ __launch_bounds__(256) void softmax_k(float* __restrict__ S) {
    __shared__ float red[8];
    const size_t base = (size_t)blockIdx.x * LSEQ;
    const int tid = threadIdx.x;
    float4 v0 = *(float4*)(S + base + tid * 4);
    float4 v1 = *(float4*)(S + base + 1024 + tid * 4);
    float m = fmaxf(fmaxf(fmaxf(v0.x, v0.y), fmaxf(v0.z, v0.w)),
                    fmaxf(fmaxf(v1.x, v1.y), fmaxf(v1.z, v1.w)));
    #pragma unroll
    for (int o = 16; o; o >>= 1) m = fmaxf(m, __shfl_xor_sync(0xFFFFFFFFu, m, o));
    if ((tid & 31) == 0) red[tid >> 5] = m;
    __syncthreads();
    float mx = red[0];
    #pragma unroll
    for (int i = 1; i < 8; i++) mx = fmaxf(mx, red[i]);
    __syncthreads();
    v0.x = __expf(v0.x - mx); v0.y = __expf(v0.y - mx);
    v0.z = __expf(v0.z - mx); v0.w = __expf(v0.w - mx);
    v1.x = __expf(v1.x - mx); v1.y = __expf(v1.y - mx);
    v1.z = __expf(v1.z - mx); v1.w = __expf(v1.w - mx);
    float s = v0.x + v0.y + v0.z + v0.w + v1.x + v1.y + v1.z + v1.w;
    #pragma unroll
    for (int o = 16; o; o >>= 1) s += __shfl_xor_sync(0xFFFFFFFFu, s, o);
    if ((tid & 31) == 0) red[tid >> 5] = s;
    __syncthreads();
    float tot = 0.f;
    #pragma unroll
    for (int i = 0; i < 8; i++) tot += red[i];
    const float inv = 1.0f / tot;
    v0.x *= inv; v0.y *= inv; v0.z *= inv; v0.w *= inv;
    v1.x *= inv; v1.y *= inv; v1.z *= inv; v1.w *= inv;
    *(float4*)(S + base + tid * 4) = v0;
    *(float4*)(S + base + 1024 + tid * 4) = v1;
}

// ============================================================================
// Transpose V per (b,h): vt[z][d][t] = qkv[b*L+t][2D + h*128 + d]
// ============================================================================
__global__ __launch_bounds__(256) void transpose_v_k(const float* __restrict__ qkv,
                                                     float* __restrict__ vt) {
    __shared__ float tile[32][33];
    const int z = blockIdx.z, zo = z >> 4, zi = z & 15;
    const float* src = qkv + (size_t)zo * LSEQ * QKVDIM + 2 * DIM + zi * HDIM;
    float* dst = vt + (size_t)z * HDIM * LSEQ;
    const int t0 = blockIdx.x * 32, d0 = blockIdx.y * 32;
    const int tx = threadIdx.x & 31, ty = threadIdx.x >> 5;
    #pragma unroll
    for (int r = ty; r < 32; r += 8)
        tile[r][tx] = src[(size_t)(t0 + r) * QKVDIM + d0 + tx];
    __syncthreads();
    #pragma unroll
    for (int r = ty; r < 32; r += 8)
        dst[(size_t)(d0 + r) * LSEQ + t0 + tx] = tile[tx][r];
}

// ============================================================================
// tf32 tensor-core GEMM, cp.async 3-stage pipeline:
//   C = epi(alpha * A @ B^T); A:[M,K] row-major, B:[N,K] row-major.
//   BM=BN=128, BK=32. 8 warps (2x4), warp tile 64x32, m16n8k8 frags.
//   Raw fp32 in SMEM (XOR swizzle, stride 32); cvt.rna.tf32 at frag load.
//   EPI: 0=none 1=+Dm 2=relu 3=*Dm. Batched z with two-level offsets.
// ============================================================================
#define STAGES  3
#define TILE_W  (128 * 32)                    // words per tile (16KB)
#define STG_W   (2 * TILE_W)                  // A+B per stage
#define SM_TOT  (STAGES * STG_W * 4)          // 98304 bytes

__device__ __forceinline__ uint32_t smem_u32(const void* p) {
    uint32_t a;
    asm("{ .reg .u64 t; cvta.to.shared.u64 t, %1; cvt.u32.u64 %0, t; }"
        : "=r"(a) : "l"(p));
    return a;
}
__device__ __forceinline__ uint32_t f2tf(uint32_t raw) {
    uint32_t u;
    asm("cvt.rna.tf32.f32 %0, %1;" : "=r"(u) : "f"(__uint_as_float(raw)));
    return u;
}
__device__ __forceinline__ void mma8(float c[4], const uint32_t a[4],
                                     uint32_t b0, uint32_t b1) {
    asm volatile(
        "mma.sync.aligned.m16n8k8.row.col.f32.tf32.tf32.f32 "
        "{%0,%1,%2,%3}, {%4,%5,%6,%7}, {%8,%9}, {%0,%1,%2,%3};"
        : "+f"(c[0]), "+f"(c[1]), "+f"(c[2]), "+f"(c[3])
        : "r"(a[0]), "r"(a[1]), "r"(a[2]), "r"(a[3]), "r"(b0), "r"(b1));
}
__device__ __forceinline__ void cp16(uint32_t dst, const float* src) {
    asm volatile("cp.async.cg.shared.global [%0], [%1], 16;"
                 :: "r"(dst), "l"(src) : "memory");
}

// issue one 128x32 tile into stage buffer (XOR-swizzled), 256 threads
__device__ __forceinline__ void issue_tile(uint32_t sbuf, const float* __restrict__ P,
                                           int ld, int row0, int k0, int tid) {
    #pragma unroll
    for (int r = 0; r < 4; r++) {
        int idx = tid + 256 * r;
        int row = idx >> 3, c4 = idx & 7;
        int g = c4 ^ (row & 7);
        cp16(sbuf + (uint32_t)(row * 32 + g * 4) * 4,
             P + (size_t)(row0 + row) * ld + k0 + c4 * 4);
    }
}

template <int EPI>
__global__ __launch_bounds__(256, 2) void tfgemm_k(
    const float* __restrict__ A, int lda, size_t soA, size_t siA,
    const float* __restrict__ B, int ldb, size_t soB, size_t siB,
    float* __restrict__ C, int ldc, size_t soC, size_t siC,
    const float* __restrict__ Dm, int ldd, size_t soD, size_t siD,
    int K, int zdiv, float alpha) {

    extern __shared__ uint32_t smw[];
    const uint32_t sbase = smem_u32(smw);

    const int tid = threadIdx.x, wid = tid >> 5, lane = tid & 31;
    const int qr = lane >> 2, qc = lane & 3;
    const int wm = (wid >> 2) * 64;   // 0 or 64
    const int wn = (wid & 3) * 32;    // 0,32,64,96

    const int z = blockIdx.z, zo = z / zdiv, zi = z % zdiv;
    A += (size_t)zo * soA + (size_t)zi * siA;
    B += (size_t)zo * soB + (size_t)zi * siB;
    C += (size_t)zo * soC + (size_t)zi * siC;
    if (EPI == 1 || EPI == 3) Dm += (size_t)zo * soD + (size_t)zi * siD;

    const int m0 = blockIdx.y * 128;
    const int n0 = blockIdx.x * 128;

    float acc[4][4][4];
    #pragma unroll
    for (int i = 0; i < 4; i++)
        #pragma unroll
        for (int j = 0; j < 4; j++)
            #pragma unroll
            for (int r = 0; r < 4; r++) acc[i][j][r] = 0.f;

    const int T = K / 32;

    // prologue: issue stages 0..STAGES-2
    #pragma unroll
    for (int s = 0; s < STAGES - 1; s++) {
        if (s < T) {
            issue_tile(sbase + s * STG_W * 4,            A, lda, m0, s * 32, tid);
            issue_tile(sbase + (s * STG_W + TILE_W) * 4, B, ldb, n0, s * 32, tid);
        }
        asm volatile("cp.async.commit_group;" ::: "memory");
    }

    for (int i = 0; i < T; i++) {
        asm volatile("cp.async.wait_group 1;" ::: "memory");
        __syncthreads();

        const int st = i % STAGES;
        const uint32_t* As = smw + st * STG_W;
        const uint32_t* Bs = As + TILE_W;

        #pragma unroll
        for (int ks = 0; ks < 4; ks++) {
            const int g0 = (2 * ks), g1 = (2 * ks + 1);
            uint32_t af[4][4];
            #pragma unroll
            for (int mf = 0; mf < 4; mf++) {
                const int row = wm + mf * 16 + qr;       // row&7 == qr
                const uint32_t* p0 = As + row * 32;
                const uint32_t* p1 = As + (row + 8) * 32;
                af[mf][0] = f2tf(p0[(g0 ^ qr) * 4 + qc]);
                af[mf][1] = f2tf(p1[(g0 ^ qr) * 4 + qc]);
                af[mf][2] = f2tf(p0[(g1 ^ qr) * 4 + qc]);
                af[mf][3] = f2tf(p1[(g1 ^ qr) * 4 + qc]);
            }
            #pragma unroll
            for (int nf = 0; nf < 4; nf++) {
                const int row = wn + nf * 8 + qr;        // row&7 == qr
                const uint32_t* p = Bs + row * 32;
                uint32_t b0 = f2tf(p[(g0 ^ qr) * 4 + qc]);
                uint32_t b1 = f2tf(p[(g1 ^ qr) * 4 + qc]);
                #pragma unroll
                for (int mf = 0; mf < 4; mf++)
                    mma8(acc[mf][nf], af[mf], b0, b1);
            }
        }

        __syncthreads();
        const int nk = i + STAGES - 1;
        if (nk < T) {
            const int ns = nk % STAGES;
            issue_tile(sbase + ns * STG_W * 4,            A, lda, m0, nk * 32, tid);
            issue_tile(sbase + (ns * STG_W + TILE_W) * 4, B, ldb, n0, nk * 32, tid);
        }
        asm volatile("cp.async.commit_group;" ::: "memory");
    }

    // epilogue: c0/c1 -> (row, col/col+1); c2/c3 -> (row+8, col/col+1)
    #pragma unroll
    for (int mf = 0; mf < 4; mf++) {
        #pragma unroll
        for (int half = 0; half < 2; half++) {
            const size_t row = (size_t)(m0 + wm + mf * 16 + qr + half * 8);
            #pragma unroll
            for (int nf = 0; nf < 4; nf++) {
                const int col = n0 + wn + nf * 8 + qc * 2;
                float2 v;
                v.x = acc[mf][nf][half * 2 + 0] * alpha;
                v.y = acc[mf][nf][half * 2 + 1] * alpha;
                if (EPI == 1) {
                    float2 d2 = *(const float2*)(Dm + row * ldd + col);
                    v.x += d2.x; v.y += d2.y;
                } else if (EPI == 2) {
                    v.x = fmaxf(v.x, 0.f); v.y = fmaxf(v.y, 0.f);
                } else if (EPI == 3) {
                    float2 d2 = *(const float2*)(Dm + row * ldd + col);
                    v.x *= d2.x; v.y *= d2.y;
                }
                *(float2*)(C + row * ldc + col) = v;
            }
        }
    }
}

// ============================================================================
// Host launcher
// ============================================================================
extern "C" void kernel_launch(void* const* d_in, const int* in_sizes, int n_in,
                              void* d_out, int out_size) {
    const float* x          = (const float*)d_in[0];
    const float* w_qkv      = (const float*)d_in[1];
    const float* w_out      = (const float*)d_in[2];
    const float* w_in       = (const float*)d_in[3];
    const float* w_hidden   = (const float*)d_in[4];
    const float* w_gate     = (const float*)d_in[5];
    const float* g_attnnorm = (const float*)d_in[6];
    const float* g_ffnnorm  = (const float*)d_in[7];

    float* out    = (float*)d_out;
    float* scores = out + (size_t)NTOK * DIM;

    float *xn, *qkv, *attn, *after, *hidden, *hg, *vt;
    cudaGetSymbolAddress((void**)&xn,     g_xn);
    cudaGetSymbolAddress((void**)&qkv,    g_qkv);
    cudaGetSymbolAddress((void**)&attn,   g_attn);
    cudaGetSymbolAddress((void**)&after,  g_after);
    cudaGetSymbolAddress((void**)&hidden, g_hidden);
    cudaGetSymbolAddress((void**)&hg,     g_hg);
    cudaGetSymbolAddress((void**)&vt,     g_vt);

    static bool attr_done = false;
    if (!attr_done) {
        cudaFuncSetAttribute(tfgemm_k<0>, cudaFuncAttributeMaxDynamicSharedMemorySize, SM_TOT);
        cudaFuncSetAttribute(tfgemm_k<1>, cudaFuncAttributeMaxDynamicSharedMemorySize, SM_TOT);
        cudaFuncSetAttribute(tfgemm_k<2>, cudaFuncAttributeMaxDynamicSharedMemorySize, SM_TOT);
        cudaFuncSetAttribute(tfgemm_k<3>, cudaFuncAttributeMaxDynamicSharedMemorySize, SM_TOT);
        attr_done = true;
    }

    const size_t slabS = (size_t)LSEQ * LSEQ;
    const size_t bQKV  = (size_t)LSEQ * QKVDIM;
    const size_t bTOK  = (size_t)LSEQ * DIM;
    const size_t hVT   = (size_t)HDIM * LSEQ;
    const float invsqrt = 0.08838834764831845f;   // 1/sqrt(128)

    // 1) attn rmsnorm
    rmsnorm_k<<<NTOK, 256>>>(x, g_attnnorm, xn);

    // 2) qkv = xn @ w_qkv^T : M=4096, N=6144, K=2048
    tfgemm_k<0><<<dim3(QKVDIM / 128, NTOK / 128, 1), 256, SM_TOT>>>(
        xn, DIM, 0, 0, w_qkv, DIM, 0, 0, qkv, QKVDIM, 0, 0,
        nullptr, 0, 0, 0, DIM, 1, 1.0f);

    // 3) transpose V per head (K-major B for attn@V)
    transpose_v_k<<<dim3(LSEQ / 32, HDIM / 32, NB * NH), 256>>>(qkv, vt);

    // 4) scores = (Q @ K^T)/sqrt(HD) : per z, M=N=2048, K=128
    tfgemm_k<0><<<dim3(LSEQ / 128, LSEQ / 128, NB * NH), 256, SM_TOT>>>(
        qkv,       QKVDIM, bQKV, HDIM,
        qkv + DIM, QKVDIM, bQKV, HDIM,
        scores,    LSEQ,   (size_t)NH * slabS, slabS,
        nullptr, 0, 0, 0, HDIM, NH, invsqrt);

    // 5) softmax
    softmax_k<<<NB * NH * LSEQ, 256>>>(scores);

    // 6) attn = scores @ V : per z, M=2048, N=128, K=2048
    tfgemm_k<0><<<dim3(1, LSEQ / 128, NB * NH), 256, SM_TOT>>>(
        scores, LSEQ, (size_t)NH * slabS, slabS,
        vt,     LSEQ, (size_t)NH * hVT,   hVT,
        attn,   DIM,  bTOK, HDIM,
        nullptr, 0, 0, 0, LSEQ, NH, 1.0f);

    // 7) after = x + attn @ w_out^T
    tfgemm_k<1><<<dim3(DIM / 128, NTOK / 128, 1), 256, SM_TOT>>>(
        attn, DIM, 0, 0, w_out, DIM, 0, 0, after, DIM, 0, 0,
        x, DIM, 0, 0, DIM, 1, 1.0f);

    // 8) ffn rmsnorm
    rmsnorm_k<<<NTOK, 256>>>(after, g_ffnnorm, xn);

    // 9) hidden = relu(yn @ w_in^T)
    tfgemm_k<2><<<dim3(DIM / 128, NTOK / 128, 1), 256, SM_TOT>>>(
        xn, DIM, 0, 0, w_in, DIM, 0, 0, hidden, DIM, 0, 0,
        nullptr, 0, 0, 0, DIM, 1, 1.0f);

    // 10) hg = hidden * (hidden @ w_gate^T)
    tfgemm_k<3><<<dim3(DIM / 128, NTOK / 128, 1), 256, SM_TOT>>>(
        hidden, DIM, 0, 0, w_gate, DIM, 0, 0, hg, DIM, 0, 0,
        hidden, DIM, 0, 0, DIM, 1, 1.0f);

    // 11) out = after + hg @ w_hidden^T
    tfgemm_k<1><<<dim3(DIM / 128, NTOK / 128, 1), 256, SM_TOT>>>(
        hg, DIM, 0, 0, w_hidden, DIM, 0, 0, out, DIM, 0, 0,
        after, DIM, 0, 0, DIM, 1, 1.0f);
}